// round 15
// baseline (speedup 1.0000x reference)
#include <cuda_runtime.h>
#include <cuda_fp16.h>
#include <math.h>
#include <stdint.h>

// Shapes fixed by dataset: x[8,2048,1024] f32, Wg[1024,8], W1[8,1024,2048],
// W2[8,2048,1024]. T = 16384 tokens, top-2 of 8 experts.
#define HDIM 1024
#define FDIM 2048
#define NE   8
#define MAXT 16384

// ------------------- device-global scratch ------------------------------
__device__ int   g_ecnt[NE];
__device__ int   g_off[NE + 1];
__device__ int   g_etok[NE * MAXT];
__device__ float g_ecw [NE * MAXT];
__device__ int   g_pos [2 * MAXT];     // per token: e*MAXT+slot, two entries
__device__ float g_zacc;
__device__ int   g_cnt0, g_cnt1;
__device__ float g_sumw0, g_sumw1;
// fp16 operands. Weights stored TRANSPOSED: w1t [e][F][H], w2t [e][H][F]
__device__ __half g_x [(size_t)MAXT * HDIM];
__device__ __half g_w1[(size_t)NE * HDIM * FDIM];
__device__ __half g_w2[(size_t)NE * FDIM * HDIM];
// hidden activations (compacted rows), K-contiguous [2T][F]
__device__ __half g_h [(size_t)2 * MAXT * FDIM];
// gemm2 per-(expert,slot) weighted outputs, compact rows [2T][H] f32
__device__ float  g_o2[(size_t)2 * MAXT * HDIM];

// ------------------- helpers --------------------------------------------
__device__ __forceinline__ uint32_t smem_u32(const void* p) {
    uint32_t a;
    asm("{ .reg .u64 t; cvta.to.shared.u64 t, %1; cvt.u32.u64 %0, t; }"
        : "=r"(a) : "l"(p));
    return a;
}
__device__ __forceinline__ void cpa16(uint32_t dst, const void* src, bool valid) {
    int sz = valid ? 16 : 0;
    asm volatile("cp.async.cg.shared.global [%0], [%1], 16, %2;"
                 :: "r"(dst), "l"(src), "r"(sz) : "memory");
}
__device__ __forceinline__ void cpa_commit() {
    asm volatile("cp.async.commit_group;" ::: "memory");
}
__device__ __forceinline__ void mma_f16(float* c, const uint32_t* a, const uint32_t* b) {
    asm volatile(
        "mma.sync.aligned.m16n8k16.row.col.f32.f16.f16.f32 "
        "{%0,%1,%2,%3}, {%4,%5,%6,%7}, {%8,%9}, {%0,%1,%2,%3};"
        : "+f"(c[0]), "+f"(c[1]), "+f"(c[2]), "+f"(c[3])
        : "r"(a[0]), "r"(a[1]), "r"(a[2]), "r"(a[3]), "r"(b[0]), "r"(b[1]));
}
__device__ __forceinline__ void ldsm4(uint32_t addr, uint32_t* r) {
    asm volatile("ldmatrix.sync.aligned.m8n8.x4.shared.b16 {%0,%1,%2,%3}, [%4];"
                 : "=r"(r[0]), "=r"(r[1]), "=r"(r[2]), "=r"(r[3]) : "r"(addr));
}

// SMEM tile geometry: K-tile 32, rows 80 B (64 B payload + 16 pad).
// CTA tile 128(M) x 256(N): A seg 128 rows, B seg 256 rows.
#define ROWB 80
#define ASEG 10240           // 128 rows * 80 B
#define STAGEB 30720         // A | B
#define NSTAGE 4
#define SMEM_BYTES (NSTAGE * STAGEB)   // 122880

// ------------------- reset (counters only) -------------------------------
__global__ void reset_kernel() {
    if (threadIdx.x == 0) {
        g_zacc = 0.0f; g_cnt0 = 0; g_cnt1 = 0;
        g_sumw0 = 0.0f; g_sumw1 = 0.0f;
    }
    if (threadIdx.x < NE) g_ecnt[threadIdx.x] = 0;
}

// ================= fused prep: router | cvt_x | tsplit W1 | tsplit W2 =====
#define PREP_ROUTER_BLKS 2048
#define PREP_CVT_BLKS    1024
#define PREP_W1_BLKS     ((FDIM / 32) * (HDIM / 32) * NE)   // 16384
#define PREP_W2_BLKS     ((HDIM / 32) * (FDIM / 32) * NE)   // 16384
#define PREP_GRID (PREP_ROUTER_BLKS + PREP_CVT_BLKS + PREP_W1_BLKS + PREP_W2_BLKS)

__device__ __forceinline__ void prep_router(const float* __restrict__ x,
                                            const float* __restrict__ Wg,
                                            int blk, int T) {
    int warp = (blk * 256 + (int)threadIdx.x) >> 5;
    int lane = threadIdx.x & 31;
    if (warp >= T) return;
    const float* xr = x + (size_t)warp * HDIM;

    float acc[NE];
#pragma unroll
    for (int e = 0; e < NE; ++e) acc[e] = 0.0f;
    for (int i = lane; i < HDIM; i += 32) {
        float xv = xr[i];
        float4 w0 = *(const float4*)(Wg + (size_t)i * NE);
        float4 w1 = *(const float4*)(Wg + (size_t)i * NE + 4);
        acc[0] += xv * w0.x; acc[1] += xv * w0.y;
        acc[2] += xv * w0.z; acc[3] += xv * w0.w;
        acc[4] += xv * w1.x; acc[5] += xv * w1.y;
        acc[6] += xv * w1.z; acc[7] += xv * w1.w;
    }
#pragma unroll
    for (int off = 16; off > 0; off >>= 1)
#pragma unroll
        for (int e = 0; e < NE; ++e)
            acc[e] += __shfl_xor_sync(0xFFFFFFFFu, acc[e], off);

    if (lane == 0) {
        float m = acc[0];
#pragma unroll
        for (int e = 1; e < NE; ++e) m = fmaxf(m, acc[e]);
        float p[NE], s = 0.0f;
#pragma unroll
        for (int e = 0; e < NE; ++e) { p[e] = __expf(acc[e] - m); s += p[e]; }
        float lse = m + logf(s);
        atomicAdd(&g_zacc, lse * lse);

        int i0 = 0;
#pragma unroll
        for (int e = 1; e < NE; ++e) if (p[e] > p[i0]) i0 = e;
        int i1 = (i0 == 0) ? 1 : 0;
#pragma unroll
        for (int e = 0; e < NE; ++e) if (e != i0 && p[e] > p[i1]) i1 = e;
        float w0 = p[i0] / s, w1 = p[i1] / s;

        atomicAdd(&g_sumw0, w0);
        atomicAdd(&g_sumw1, w1);
        if (i0 == 0 || i1 == 0) atomicAdd(&g_cnt0, 1);
        if (i0 == 1 || i1 == 1) atomicAdd(&g_cnt1, 1);

        int p0 = atomicAdd(&g_ecnt[i0], 1);
        g_etok[i0 * MAXT + p0] = warp; g_ecw[i0 * MAXT + p0] = w0;
        int p1 = atomicAdd(&g_ecnt[i1], 1);
        g_etok[i1 * MAXT + p1] = warp; g_ecw[i1 * MAXT + p1] = w1;
        g_pos[warp * 2 + 0] = i0 * MAXT + p0;
        g_pos[warp * 2 + 1] = i1 * MAXT + p1;
    }
}

__device__ __forceinline__ void prep_cvt(const float* __restrict__ src, int blk) {
    size_t n4 = (size_t)MAXT * HDIM / 4;
    for (size_t i = (size_t)blk * 256 + threadIdx.x; i < n4;
         i += (size_t)PREP_CVT_BLKS * 256) {
        float4 v = ((const float4*)src)[i];
        __half2* H = (__half2*)(g_x + i * 4);
        H[0] = __halves2half2(__float2half_rn(v.x), __float2half_rn(v.y));
        H[1] = __halves2half2(__float2half_rn(v.z), __float2half_rn(v.w));
    }
}

__device__ __forceinline__ void prep_tsplit(const float* __restrict__ src,
                                            __half* __restrict__ dst,
                                            int K, int N, int q) {
    __shared__ float t[32][33];
    int nb = N / 32;
    int nblk = q % nb;
    int kblk = (q / nb) % (K / 32);
    int e    = q / (nb * (K / 32));
    int k0 = kblk * 32, n0 = nblk * 32;
    int tx = threadIdx.x & 31, ty = threadIdx.x >> 5;
    const float* s = src + (size_t)e * K * N;
    __half* de = dst + (size_t)e * K * N;
    for (int i = ty; i < 32; i += 8)
        t[i][tx] = s[(size_t)(k0 + i) * N + n0 + tx];
    __syncthreads();
    for (int i = ty; i < 32; i += 8) {
        float v = t[tx][i];
        de[(size_t)(n0 + i) * K + k0 + tx] = __float2half_rn(v);
    }
}

__global__ void prep_kernel(const float* __restrict__ x,
                            const float* __restrict__ Wg,
                            const float* __restrict__ W1,
                            const float* __restrict__ W2, int T) {
    int b = blockIdx.x;
    if (b < PREP_ROUTER_BLKS) {
        prep_router(x, Wg, b, T);
    } else if (b < PREP_ROUTER_BLKS + PREP_CVT_BLKS) {
        prep_cvt(x, b - PREP_ROUTER_BLKS);
    } else if (b < PREP_ROUTER_BLKS + PREP_CVT_BLKS + PREP_W1_BLKS) {
        prep_tsplit(W1, g_w1, HDIM, FDIM, b - PREP_ROUTER_BLKS - PREP_CVT_BLKS);
    } else {
        prep_tsplit(W2, g_w2, FDIM, HDIM,
                    b - PREP_ROUTER_BLKS - PREP_CVT_BLKS - PREP_W1_BLKS);
    }
}

__global__ void scan_kernel() {
    if (threadIdx.x == 0) {
        int s = 0; g_off[0] = 0;
        for (int e = 0; e < NE; ++e) { s += g_ecnt[e]; g_off[e + 1] = s; }
    }
}

// ========================================================================
// GEMM core: CTA 128(M)x256(N), 16 warps (2M x 8N, warp tile 64x32),
// K-tile 32, mma.sync m16n8k16 fp16, 4-stage ring, 1 sync per TWO K-tiles.
// ========================================================================
__device__ __forceinline__ void load_tile32(
    uint32_t sb, int stage,
    const __half* a, bool av, long aoff,
    const __half* b, long boff0, long boff1,
    int tid, int kb)
{
    uint32_t buf = sb + stage * STAGEB;
    int row = tid >> 2;                // 0..127
    int ch  = tid & 3;                 // 16B chunk within 64B payload
    cpa16(buf + row * ROWB + ch * 16, a + aoff + kb + ch * 8, av);
    uint32_t db = buf + ASEG + row * ROWB + ch * 16;
    cpa16(db,              b + boff0 + kb + ch * 8, true);
    cpa16(db + 128 * ROWB, b + boff1 + kb + ch * 8, true);
}

__device__ __forceinline__ void compute_stage32(
    uint32_t sb, int stage, int moff, int noff, int lane,
    float acc[4][4][4])
{
    uint32_t base = sb + stage * STAGEB;
    int arow = lane & 15;
    int akh  = (lane >> 4) << 4;
    int brow = ((lane >> 4) & 1) * 8 + (lane & 7);
    int bkh  = ((lane >> 3) & 1) << 4;
#pragma unroll
    for (int ks = 0; ks < 2; ++ks) {
        int kby = ks * 32;
        uint32_t fa[4][4];
#pragma unroll
        for (int i = 0; i < 4; ++i) {
            uint32_t ra = base + (uint32_t)((moff + i * 16 + arow) * ROWB) +
                          kby + akh;
            ldsm4(ra, fa[i]);
        }
        uint32_t bb[2][4];
#pragma unroll
        for (int p = 0; p < 2; ++p) {
            uint32_t rb = base + ASEG +
                          (uint32_t)((noff + p * 16 + brow) * ROWB) + kby + bkh;
            ldsm4(rb, bb[p]);
        }
#pragma unroll
        for (int i = 0; i < 4; ++i)
#pragma unroll
            for (int j = 0; j < 4; ++j) {
                uint32_t* bj = &bb[j >> 1][(j & 1) * 2];
                mma_f16(acc[i][j], fa[i], bj);
            }
    }
}

// Mainloop: 2 K-tiles per barrier, 4-stage ring, wait_group 0.
#define GEMM_MAINLOOP(A_PTR, B_PTR, KT)                                       \
    load_tile32(sb, 0, A_PTR, av, aoff, B_PTR, boff0, boff1, tid, 0);         \
    cpa_commit();                                                             \
    load_tile32(sb, 1, A_PTR, av, aoff, B_PTR, boff0, boff1, tid, 32);        \
    cpa_commit();                                                             \
    for (int kt = 0; kt < (KT); kt += 2) {                                    \
        asm volatile("cp.async.wait_group 0;" ::: "memory");                  \
        __syncthreads();                                                      \
        if (kt + 2 < (KT)) {                                                  \
            load_tile32(sb, (kt + 2) & 3, A_PTR, av, aoff, B_PTR,             \
                        boff0, boff1, tid, (kt + 2) * 32);                    \
            cpa_commit();                                                     \
        }                                                                     \
        if (kt + 3 < (KT)) {                                                  \
            load_tile32(sb, (kt + 3) & 3, A_PTR, av, aoff, B_PTR,             \
                        boff0, boff1, tid, (kt + 3) * 32);                    \
            cpa_commit();                                                     \
        }                                                                     \
        compute_stage32(sb, kt & 3, moff, noff, lane, acc);                   \
        compute_stage32(sb, (kt + 1) & 3, moff, noff, lane, acc);             \
    }

// ------------------- GEMM1: h = gelu(gather(x) @ W1[e]) ------------------
__global__ __launch_bounds__(512, 1) void moe_gemm1() {
    int e = blockIdx.z;
    int n = g_ecnt[e];
    int row0 = blockIdx.y << 7;
    if (row0 >= n) return;
    int col0 = blockIdx.x << 8;

    extern __shared__ __align__(16) char smem[];
    uint32_t sb = smem_u32(smem);
    int tid = threadIdx.x, wid = tid >> 5, lane = tid & 31;
    int moff = (wid >> 3) * 64, noff = (wid & 7) * 32;

    const int* etok = g_etok + e * MAXT;
    int arow_g = row0 + (tid >> 2);
    bool av = arow_g < n;
    long aoff = av ? (long)etok[arow_g] * HDIM : 0;
    long boff0 = (long)(col0 + (tid >> 2)) * HDIM;
    long boff1 = boff0 + (long)128 * HDIM;
    const __half* W = g_w1 + (size_t)e * HDIM * FDIM;

    float acc[4][4][4];
#pragma unroll
    for (int i = 0; i < 4; ++i)
#pragma unroll
        for (int j = 0; j < 4; ++j)
#pragma unroll
            for (int q = 0; q < 4; ++q) acc[i][j][q] = 0.0f;

    GEMM_MAINLOOP(g_x, W, HDIM / 32)

    // epilogue: gelu -> fp16 h
    int lane4 = lane >> 2, lanec = (lane & 3) * 2;
    int hbase = g_off[e];
#pragma unroll
    for (int i = 0; i < 4; ++i) {
#pragma unroll
        for (int rr = 0; rr < 2; ++rr) {
            int r = row0 + moff + i * 16 + lane4 + rr * 8;
            if (r < n) {
                size_t base = (size_t)(hbase + r) * FDIM + col0 + noff;
#pragma unroll
                for (int j = 0; j < 4; ++j) {
                    float vA = acc[i][j][rr * 2 + 0];
                    float vB = acc[i][j][rr * 2 + 1];
                    float gA = 0.5f * vA * (1.0f + erff(vA * 0.70710678118654752f));
                    float gB = 0.5f * vB * (1.0f + erff(vB * 0.70710678118654752f));
                    *(__half2*)(g_h + base + j * 8 + lanec) =
                        __halves2half2(__float2half_rn(gA), __float2half_rn(gB));
                }
            }
        }
    }
}

// ------------------- GEMM2: g_o2[row] = cw * (h @ W2[e]) ------------------
__global__ __launch_bounds__(512, 1) void moe_gemm2() {
    int e = blockIdx.z;
    int n = g_ecnt[e];
    int row0 = blockIdx.y << 7;
    if (row0 >= n) return;
    int col0 = blockIdx.x << 8;

    extern __shared__ __align__(16) char smem[];
    uint32_t sb = smem_u32(smem);
    int tid = threadIdx.x, wid = tid >> 5, lane = tid & 31;
    int moff = (wid >> 3) * 64, noff = (wid & 7) * 32;

    int hbase = g_off[e];
    int arow_g = row0 + (tid >> 2);
    bool av = arow_g < n;
    long aoff = (long)(hbase + arow_g) * FDIM;
    long boff0 = (long)(col0 + (tid >> 2)) * FDIM;
    long boff1 = boff0 + (long)128 * FDIM;
    const __half* W = g_w2 + (size_t)e * FDIM * HDIM;

    float acc[4][4][4];
#pragma unroll
    for (int i = 0; i < 4; ++i)
#pragma unroll
        for (int j = 0; j < 4; ++j)
#pragma unroll
            for (int q = 0; q < 4; ++q) acc[i][j][q] = 0.0f;

    GEMM_MAINLOOP(g_h, W, FDIM / 32)

    // epilogue: weighted plain stores into compact g_o2 (no atomics)
    int lane4 = lane >> 2, lanec = (lane & 3) * 2;
#pragma unroll
    for (int i = 0; i < 4; ++i) {
#pragma unroll
        for (int rr = 0; rr < 2; ++rr) {
            int r = row0 + moff + i * 16 + lane4 + rr * 8;
            if (r < n) {
                float w = g_ecw[e * MAXT + r];
                float* orow = g_o2 + (size_t)(hbase + r) * HDIM + col0 + noff;
#pragma unroll
                for (int j = 0; j < 4; ++j) {
                    float2 v;
                    v.x = w * acc[i][j][rr * 2 + 0];
                    v.y = w * acc[i][j][rr * 2 + 1];
                    *(float2*)(orow + j * 8 + lanec) = v;
                }
            }
        }
    }
}

// ------------------- combine: out[t] = o2[pos0(t)] + o2[pos1(t)] ----------
__global__ void combine_kernel(float* __restrict__ out, int T) {
    size_t n4 = (size_t)T * HDIM / 4;
    for (size_t i = (size_t)blockIdx.x * blockDim.x + threadIdx.x; i < n4;
         i += (size_t)gridDim.x * blockDim.x) {
        int t = (int)(i / (HDIM / 4));
        int c4 = (int)(i % (HDIM / 4));
        int p0 = g_pos[t * 2 + 0], p1 = g_pos[t * 2 + 1];
        int cr0 = g_off[p0 >> 14] + (p0 & (MAXT - 1));
        int cr1 = g_off[p1 >> 14] + (p1 & (MAXT - 1));
        float4 a = *(const float4*)(g_o2 + (size_t)cr0 * HDIM + c4 * 4);
        float4 b = *(const float4*)(g_o2 + (size_t)cr1 * HDIM + c4 * 4);
        float4 r;
        r.x = a.x + b.x; r.y = a.y + b.y; r.z = a.z + b.z; r.w = a.w + b.w;
        *(float4*)(out + i * 4) = r;
    }
}

// ------------------- losses ---------------------------------------------
__global__ void finalize_kernel(float* __restrict__ out, long long out_size, int T) {
    if (blockIdx.x == 0 && threadIdx.x == 0) {
        long long base = (long long)T * HDIM;
        float invT = 1.0f / (float)T;
        float z = g_zacc * invT;
        float tpe0 = (float)g_cnt0 * invT, tpe1 = (float)g_cnt1 * invT;
        float rpp0 = g_sumw0 * invT,       rpp1 = g_sumw1 * invT;
        float aux = 2.0f * (tpe0 * rpp0 + tpe1 * rpp1);
        if (base < out_size)     out[base]     = z;
        if (base + 1 < out_size) out[base + 1] = aux;
    }
}

// ------------------- launch ---------------------------------------------
extern "C" void kernel_launch(void* const* d_in, const int* in_sizes, int n_in,
                              void* d_out, int out_size) {
    const float* x  = (const float*)d_in[0];
    const float* Wg = (const float*)d_in[1];
    const float* W1 = (const float*)d_in[2];
    const float* W2 = (const float*)d_in[3];
    float* out = (float*)d_out;
    int T = in_sizes[0] / HDIM;  // 16384

    cudaFuncSetAttribute(moe_gemm1, cudaFuncAttributeMaxDynamicSharedMemorySize, SMEM_BYTES);
    cudaFuncSetAttribute(moe_gemm2, cudaFuncAttributeMaxDynamicSharedMemorySize, SMEM_BYTES);

    reset_kernel<<<1, 32>>>();
    prep_kernel<<<PREP_GRID, 256>>>(x, Wg, W1, W2, T);
    scan_kernel<<<1, 32>>>();
    moe_gemm1<<<dim3(FDIM / 256, MAXT / 128, NE), 512, SMEM_BYTES>>>();
    moe_gemm2<<<dim3(HDIM / 256, MAXT / 128, NE), 512, SMEM_BYTES>>>();
    combine_kernel<<<2048, 256>>>(out, T);
    finalize_kernel<<<1, 32>>>(out, (long long)out_size, T);
}

// round 16
// speedup vs baseline: 1.0295x; 1.0295x over previous
#include <cuda_runtime.h>
#include <cuda_fp16.h>
#include <math.h>
#include <stdint.h>

// Shapes fixed by dataset: x[8,2048,1024] f32, Wg[1024,8], W1[8,1024,2048],
// W2[8,2048,1024]. T = 16384 tokens, top-2 of 8 experts.
#define HDIM 1024
#define FDIM 2048
#define NE   8
#define MAXT 16384

// ------------------- device-global scratch ------------------------------
__device__ int   g_ecnt[NE];
__device__ int   g_off[NE + 1];
__device__ int   g_etok[NE * MAXT];
__device__ float g_ecw [NE * MAXT];
__device__ int   g_pos [2 * MAXT];     // per token: e*MAXT+slot, two entries
__device__ float g_zacc;
__device__ int   g_cnt0, g_cnt1;
__device__ float g_sumw0, g_sumw1;
// fp16 operands. Weights stored TRANSPOSED: w1t [e][F][H], w2t [e][H][F]
__device__ __half g_x [(size_t)MAXT * HDIM];
__device__ __half g_w1[(size_t)NE * HDIM * FDIM];
__device__ __half g_w2[(size_t)NE * FDIM * HDIM];
// hidden activations (compacted rows), K-contiguous [2T][F]
__device__ __half g_h [(size_t)2 * MAXT * FDIM];
// gemm2 per-(expert,slot) weighted outputs, compact rows [2T][H] f32
__device__ float  g_o2[(size_t)2 * MAXT * HDIM];

// ------------------- helpers --------------------------------------------
__device__ __forceinline__ uint32_t smem_u32(const void* p) {
    uint32_t a;
    asm("{ .reg .u64 t; cvta.to.shared.u64 t, %1; cvt.u32.u64 %0, t; }"
        : "=r"(a) : "l"(p));
    return a;
}
__device__ __forceinline__ void cpa16(uint32_t dst, const void* src, bool valid) {
    int sz = valid ? 16 : 0;
    asm volatile("cp.async.cg.shared.global [%0], [%1], 16, %2;"
                 :: "r"(dst), "l"(src), "r"(sz) : "memory");
}
__device__ __forceinline__ void cpa_commit() {
    asm volatile("cp.async.commit_group;" ::: "memory");
}
__device__ __forceinline__ void mma_f16(float* c, const uint32_t* a, const uint32_t* b) {
    asm volatile(
        "mma.sync.aligned.m16n8k16.row.col.f32.f16.f16.f32 "
        "{%0,%1,%2,%3}, {%4,%5,%6,%7}, {%8,%9}, {%0,%1,%2,%3};"
        : "+f"(c[0]), "+f"(c[1]), "+f"(c[2]), "+f"(c[3])
        : "r"(a[0]), "r"(a[1]), "r"(a[2]), "r"(a[3]), "r"(b[0]), "r"(b[1]));
}
__device__ __forceinline__ void ldsm4(uint32_t addr, uint32_t* r) {
    asm volatile("ldmatrix.sync.aligned.m8n8.x4.shared.b16 {%0,%1,%2,%3}, [%4];"
                 : "=r"(r[0]), "=r"(r[1]), "=r"(r[2]), "=r"(r[3]) : "r"(addr));
}

// SMEM tile geometry: K-tile 32, rows 80 B (64 B payload + 16 pad).
// CTA tile 128(M) x 256(N): A seg 128 rows, B seg 256 rows.
#define ROWB 80
#define ASEG 10240           // 128 rows * 80 B
#define STAGEB 30720         // A | B
#define NSTAGE 4
#define SMEM_BYTES (NSTAGE * STAGEB)   // 122880

// ------------------- reset (counters only) -------------------------------
__global__ void reset_kernel() {
    if (threadIdx.x == 0) {
        g_zacc = 0.0f; g_cnt0 = 0; g_cnt1 = 0;
        g_sumw0 = 0.0f; g_sumw1 = 0.0f;
    }
    if (threadIdx.x < NE) g_ecnt[threadIdx.x] = 0;
}

// ================= fused prep: router | cvt_x | tsplit W1 | tsplit W2 =====
#define PREP_ROUTER_BLKS 2048
#define PREP_CVT_BLKS    1024
#define PREP_W1_BLKS     ((FDIM / 32) * (HDIM / 32) * NE)   // 16384
#define PREP_W2_BLKS     ((HDIM / 32) * (FDIM / 32) * NE)   // 16384
#define PREP_GRID (PREP_ROUTER_BLKS + PREP_CVT_BLKS + PREP_W1_BLKS + PREP_W2_BLKS)

__device__ __forceinline__ void prep_router(const float* __restrict__ x,
                                            const float* __restrict__ Wg,
                                            int blk, int T) {
    int warp = (blk * 256 + (int)threadIdx.x) >> 5;
    int lane = threadIdx.x & 31;
    if (warp >= T) return;
    const float* xr = x + (size_t)warp * HDIM;

    float acc[NE];
#pragma unroll
    for (int e = 0; e < NE; ++e) acc[e] = 0.0f;
    for (int i = lane; i < HDIM; i += 32) {
        float xv = xr[i];
        float4 w0 = *(const float4*)(Wg + (size_t)i * NE);
        float4 w1 = *(const float4*)(Wg + (size_t)i * NE + 4);
        acc[0] += xv * w0.x; acc[1] += xv * w0.y;
        acc[2] += xv * w0.z; acc[3] += xv * w0.w;
        acc[4] += xv * w1.x; acc[5] += xv * w1.y;
        acc[6] += xv * w1.z; acc[7] += xv * w1.w;
    }
#pragma unroll
    for (int off = 16; off > 0; off >>= 1)
#pragma unroll
        for (int e = 0; e < NE; ++e)
            acc[e] += __shfl_xor_sync(0xFFFFFFFFu, acc[e], off);

    if (lane == 0) {
        float m = acc[0];
#pragma unroll
        for (int e = 1; e < NE; ++e) m = fmaxf(m, acc[e]);
        float p[NE], s = 0.0f;
#pragma unroll
        for (int e = 0; e < NE; ++e) { p[e] = __expf(acc[e] - m); s += p[e]; }
        float lse = m + logf(s);
        atomicAdd(&g_zacc, lse * lse);

        int i0 = 0;
#pragma unroll
        for (int e = 1; e < NE; ++e) if (p[e] > p[i0]) i0 = e;
        int i1 = (i0 == 0) ? 1 : 0;
#pragma unroll
        for (int e = 0; e < NE; ++e) if (e != i0 && p[e] > p[i1]) i1 = e;
        float w0 = p[i0] / s, w1 = p[i1] / s;

        atomicAdd(&g_sumw0, w0);
        atomicAdd(&g_sumw1, w1);
        if (i0 == 0 || i1 == 0) atomicAdd(&g_cnt0, 1);
        if (i0 == 1 || i1 == 1) atomicAdd(&g_cnt1, 1);

        int p0 = atomicAdd(&g_ecnt[i0], 1);
        g_etok[i0 * MAXT + p0] = warp; g_ecw[i0 * MAXT + p0] = w0;
        int p1 = atomicAdd(&g_ecnt[i1], 1);
        g_etok[i1 * MAXT + p1] = warp; g_ecw[i1 * MAXT + p1] = w1;
        g_pos[warp * 2 + 0] = i0 * MAXT + p0;
        g_pos[warp * 2 + 1] = i1 * MAXT + p1;
    }
}

__device__ __forceinline__ void prep_cvt(const float* __restrict__ src, int blk) {
    size_t n4 = (size_t)MAXT * HDIM / 4;
    for (size_t i = (size_t)blk * 256 + threadIdx.x; i < n4;
         i += (size_t)PREP_CVT_BLKS * 256) {
        float4 v = ((const float4*)src)[i];
        __half2* H = (__half2*)(g_x + i * 4);
        H[0] = __halves2half2(__float2half_rn(v.x), __float2half_rn(v.y));
        H[1] = __halves2half2(__float2half_rn(v.z), __float2half_rn(v.w));
    }
}

__device__ __forceinline__ void prep_tsplit(const float* __restrict__ src,
                                            __half* __restrict__ dst,
                                            int K, int N, int q) {
    __shared__ float t[32][33];
    int nb = N / 32;
    int nblk = q % nb;
    int kblk = (q / nb) % (K / 32);
    int e    = q / (nb * (K / 32));
    int k0 = kblk * 32, n0 = nblk * 32;
    int tx = threadIdx.x & 31, ty = threadIdx.x >> 5;
    const float* s = src + (size_t)e * K * N;
    __half* de = dst + (size_t)e * K * N;
    for (int i = ty; i < 32; i += 8)
        t[i][tx] = s[(size_t)(k0 + i) * N + n0 + tx];
    __syncthreads();
    for (int i = ty; i < 32; i += 8) {
        float v = t[tx][i];
        de[(size_t)(n0 + i) * K + k0 + tx] = __float2half_rn(v);
    }
}

__global__ void prep_kernel(const float* __restrict__ x,
                            const float* __restrict__ Wg,
                            const float* __restrict__ W1,
                            const float* __restrict__ W2, int T) {
    int b = blockIdx.x;
    if (b < PREP_ROUTER_BLKS) {
        prep_router(x, Wg, b, T);
    } else if (b < PREP_ROUTER_BLKS + PREP_CVT_BLKS) {
        prep_cvt(x, b - PREP_ROUTER_BLKS);
    } else if (b < PREP_ROUTER_BLKS + PREP_CVT_BLKS + PREP_W1_BLKS) {
        prep_tsplit(W1, g_w1, HDIM, FDIM, b - PREP_ROUTER_BLKS - PREP_CVT_BLKS);
    } else {
        prep_tsplit(W2, g_w2, FDIM, HDIM,
                    b - PREP_ROUTER_BLKS - PREP_CVT_BLKS - PREP_W1_BLKS);
    }
}

__global__ void scan_kernel() {
    if (threadIdx.x == 0) {
        int s = 0; g_off[0] = 0;
        for (int e = 0; e < NE; ++e) { s += g_ecnt[e]; g_off[e + 1] = s; }
    }
}

// ========================================================================
// GEMM core: CTA 128(M)x256(N), 16 warps (2M x 8N, warp tile 64x32),
// K-tile 32, mma.sync m16n8k16 fp16, 4-stage ring (3-deep prefetch),
// one load / one compute / one sync per K-tile, wait_group 2.
// ========================================================================
__device__ __forceinline__ void load_tile32(
    uint32_t sb, int stage,
    const __half* a, bool av, long aoff,
    const __half* b, long boff0, long boff1,
    int tid, int kb)
{
    uint32_t buf = sb + stage * STAGEB;
    int row = tid >> 2;                // 0..127
    int ch  = tid & 3;                 // 16B chunk within 64B payload
    cpa16(buf + row * ROWB + ch * 16, a + aoff + kb + ch * 8, av);
    uint32_t db = buf + ASEG + row * ROWB + ch * 16;
    cpa16(db,              b + boff0 + kb + ch * 8, true);
    cpa16(db + 128 * ROWB, b + boff1 + kb + ch * 8, true);
}

__device__ __forceinline__ void compute_stage32(
    uint32_t sb, int stage, int moff, int noff, int lane,
    float acc[4][4][4])
{
    uint32_t base = sb + stage * STAGEB;
    int arow = lane & 15;
    int akh  = (lane >> 4) << 4;
    int brow = ((lane >> 4) & 1) * 8 + (lane & 7);
    int bkh  = ((lane >> 3) & 1) << 4;
#pragma unroll
    for (int ks = 0; ks < 2; ++ks) {
        int kby = ks * 32;
        uint32_t fa[4][4];
#pragma unroll
        for (int i = 0; i < 4; ++i) {
            uint32_t ra = base + (uint32_t)((moff + i * 16 + arow) * ROWB) +
                          kby + akh;
            ldsm4(ra, fa[i]);
        }
        uint32_t bb[2][4];
#pragma unroll
        for (int p = 0; p < 2; ++p) {
            uint32_t rb = base + ASEG +
                          (uint32_t)((noff + p * 16 + brow) * ROWB) + kby + bkh;
            ldsm4(rb, bb[p]);
        }
#pragma unroll
        for (int i = 0; i < 4; ++i)
#pragma unroll
            for (int j = 0; j < 4; ++j) {
                uint32_t* bj = &bb[j >> 1][(j & 1) * 2];
                mma_f16(acc[i][j], fa[i], bj);
            }
    }
}

// Mainloop: 4-stage ring, 3-deep prefetch, 1 sync per K-tile, wait_group 2.
#define GEMM_MAINLOOP(A_PTR, B_PTR, KT)                                       \
    load_tile32(sb, 0, A_PTR, av, aoff, B_PTR, boff0, boff1, tid, 0);         \
    cpa_commit();                                                             \
    load_tile32(sb, 1, A_PTR, av, aoff, B_PTR, boff0, boff1, tid, 32);        \
    cpa_commit();                                                             \
    load_tile32(sb, 2, A_PTR, av, aoff, B_PTR, boff0, boff1, tid, 64);        \
    cpa_commit();                                                             \
    for (int kt = 0; kt < (KT); ++kt) {                                       \
        asm volatile("cp.async.wait_group 2;" ::: "memory");                  \
        __syncthreads();                                                      \
        if (kt + 3 < (KT))                                                    \
            load_tile32(sb, (kt + 3) & 3, A_PTR, av, aoff, B_PTR,             \
                        boff0, boff1, tid, (kt + 3) * 32);                    \
        cpa_commit();                                                         \
        compute_stage32(sb, kt & 3, moff, noff, lane, acc);                   \
    }

// ------------------- GEMM1: h = gelu(gather(x) @ W1[e]) ------------------
__global__ __launch_bounds__(512, 1) void moe_gemm1() {
    int e = blockIdx.z;
    int n = g_ecnt[e];
    int row0 = blockIdx.y << 7;
    if (row0 >= n) return;
    int col0 = blockIdx.x << 8;

    extern __shared__ __align__(16) char smem[];
    uint32_t sb = smem_u32(smem);
    int tid = threadIdx.x, wid = tid >> 5, lane = tid & 31;
    int moff = (wid >> 3) * 64, noff = (wid & 7) * 32;

    const int* etok = g_etok + e * MAXT;
    int arow_g = row0 + (tid >> 2);
    bool av = arow_g < n;
    long aoff = av ? (long)etok[arow_g] * HDIM : 0;
    long boff0 = (long)(col0 + (tid >> 2)) * HDIM;
    long boff1 = boff0 + (long)128 * HDIM;
    const __half* W = g_w1 + (size_t)e * HDIM * FDIM;

    float acc[4][4][4];
#pragma unroll
    for (int i = 0; i < 4; ++i)
#pragma unroll
        for (int j = 0; j < 4; ++j)
#pragma unroll
            for (int q = 0; q < 4; ++q) acc[i][j][q] = 0.0f;

    GEMM_MAINLOOP(g_x, W, HDIM / 32)

    // epilogue: gelu -> fp16 h
    int lane4 = lane >> 2, lanec = (lane & 3) * 2;
    int hbase = g_off[e];
#pragma unroll
    for (int i = 0; i < 4; ++i) {
#pragma unroll
        for (int rr = 0; rr < 2; ++rr) {
            int r = row0 + moff + i * 16 + lane4 + rr * 8;
            if (r < n) {
                size_t base = (size_t)(hbase + r) * FDIM + col0 + noff;
#pragma unroll
                for (int j = 0; j < 4; ++j) {
                    float vA = acc[i][j][rr * 2 + 0];
                    float vB = acc[i][j][rr * 2 + 1];
                    float gA = 0.5f * vA * (1.0f + erff(vA * 0.70710678118654752f));
                    float gB = 0.5f * vB * (1.0f + erff(vB * 0.70710678118654752f));
                    *(__half2*)(g_h + base + j * 8 + lanec) =
                        __halves2half2(__float2half_rn(gA), __float2half_rn(gB));
                }
            }
        }
    }
}

// ------------------- GEMM2: g_o2[row] = cw * (h @ W2[e]) ------------------
__global__ __launch_bounds__(512, 1) void moe_gemm2() {
    int e = blockIdx.z;
    int n = g_ecnt[e];
    int row0 = blockIdx.y << 7;
    if (row0 >= n) return;
    int col0 = blockIdx.x << 8;

    extern __shared__ __align__(16) char smem[];
    uint32_t sb = smem_u32(smem);
    int tid = threadIdx.x, wid = tid >> 5, lane = tid & 31;
    int moff = (wid >> 3) * 64, noff = (wid & 7) * 32;

    int hbase = g_off[e];
    int arow_g = row0 + (tid >> 2);
    bool av = arow_g < n;
    long aoff = (long)(hbase + arow_g) * FDIM;
    long boff0 = (long)(col0 + (tid >> 2)) * FDIM;
    long boff1 = boff0 + (long)128 * FDIM;
    const __half* W = g_w2 + (size_t)e * FDIM * HDIM;

    float acc[4][4][4];
#pragma unroll
    for (int i = 0; i < 4; ++i)
#pragma unroll
        for (int j = 0; j < 4; ++j)
#pragma unroll
            for (int q = 0; q < 4; ++q) acc[i][j][q] = 0.0f;

    GEMM_MAINLOOP(g_h, W, FDIM / 32)

    // epilogue: weighted plain stores into compact g_o2 (no atomics)
    int lane4 = lane >> 2, lanec = (lane & 3) * 2;
#pragma unroll
    for (int i = 0; i < 4; ++i) {
#pragma unroll
        for (int rr = 0; rr < 2; ++rr) {
            int r = row0 + moff + i * 16 + lane4 + rr * 8;
            if (r < n) {
                float w = g_ecw[e * MAXT + r];
                float* orow = g_o2 + (size_t)(hbase + r) * HDIM + col0 + noff;
#pragma unroll
                for (int j = 0; j < 4; ++j) {
                    float2 v;
                    v.x = w * acc[i][j][rr * 2 + 0];
                    v.y = w * acc[i][j][rr * 2 + 1];
                    *(float2*)(orow + j * 8 + lanec) = v;
                }
            }
        }
    }
}

// ------------------- combine: out[t] = o2[pos0(t)] + o2[pos1(t)] ----------
__global__ void combine_kernel(float* __restrict__ out, int T) {
    size_t n4 = (size_t)T * HDIM / 4;
    for (size_t i = (size_t)blockIdx.x * blockDim.x + threadIdx.x; i < n4;
         i += (size_t)gridDim.x * blockDim.x) {
        int t = (int)(i / (HDIM / 4));
        int c4 = (int)(i % (HDIM / 4));
        int p0 = g_pos[t * 2 + 0], p1 = g_pos[t * 2 + 1];
        int cr0 = g_off[p0 >> 14] + (p0 & (MAXT - 1));
        int cr1 = g_off[p1 >> 14] + (p1 & (MAXT - 1));
        float4 a = *(const float4*)(g_o2 + (size_t)cr0 * HDIM + c4 * 4);
        float4 b = *(const float4*)(g_o2 + (size_t)cr1 * HDIM + c4 * 4);
        float4 r;
        r.x = a.x + b.x; r.y = a.y + b.y; r.z = a.z + b.z; r.w = a.w + b.w;
        *(float4*)(out + i * 4) = r;
    }
}

// ------------------- losses ---------------------------------------------
__global__ void finalize_kernel(float* __restrict__ out, long long out_size, int T) {
    if (blockIdx.x == 0 && threadIdx.x == 0) {
        long long base = (long long)T * HDIM;
        float invT = 1.0f / (float)T;
        float z = g_zacc * invT;
        float tpe0 = (float)g_cnt0 * invT, tpe1 = (float)g_cnt1 * invT;
        float rpp0 = g_sumw0 * invT,       rpp1 = g_sumw1 * invT;
        float aux = 2.0f * (tpe0 * rpp0 + tpe1 * rpp1);
        if (base < out_size)     out[base]     = z;
        if (base + 1 < out_size) out[base + 1] = aux;
    }
}

// ------------------- launch ---------------------------------------------
extern "C" void kernel_launch(void* const* d_in, const int* in_sizes, int n_in,
                              void* d_out, int out_size) {
    const float* x  = (const float*)d_in[0];
    const float* Wg = (const float*)d_in[1];
    const float* W1 = (const float*)d_in[2];
    const float* W2 = (const float*)d_in[3];
    float* out = (float*)d_out;
    int T = in_sizes[0] / HDIM;  // 16384

    cudaFuncSetAttribute(moe_gemm1, cudaFuncAttributeMaxDynamicSharedMemorySize, SMEM_BYTES);
    cudaFuncSetAttribute(moe_gemm2, cudaFuncAttributeMaxDynamicSharedMemorySize, SMEM_BYTES);

    reset_kernel<<<1, 32>>>();
    prep_kernel<<<PREP_GRID, 256>>>(x, Wg, W1, W2, T);
    scan_kernel<<<1, 32>>>();
    moe_gemm1<<<dim3(FDIM / 256, MAXT / 128, NE), 512, SMEM_BYTES>>>();
    moe_gemm2<<<dim3(HDIM / 256, MAXT / 128, NE), 512, SMEM_BYTES>>>();
    combine_kernel<<<2048, 256>>>(out, T);
    finalize_kernel<<<1, 32>>>(out, (long long)out_size, T);
}